// round 11
// baseline (speedup 1.0000x reference)
#include <cuda_runtime.h>

// out[b,h,w] = sum_c x[b,h,w,c] * mask[h%8,w%8,c],
// mask = sigmoid(12*(sigmoid(5*w) - thresh)), x: (32,512,512,4) fp32 NHWC.
//
// R9/R10 confirmed: limiter is CTA scheduling/ramp granularity, not HBM.
// R11: (1) 64-thread blocks, 32768 blocks (backfill unit halves again);
// (2) no smem mask table, no __syncthreads -- each thread computes its ONE
// mask float4 directly (2 L2-hit loads + 8 MUFU, once), so the 4 x-loads
// issue immediately at block start with no barrier serialization.

#define PMASK_SLOPE 5.0f
#define SAMPLE_SLOPE 12.0f

#define NPIX    (32 * 512 * 512)    // 8,388,608 pixels
#define NBLOCKS (NPIX / 256)        // 32768 blocks, 256 px each

__device__ __forceinline__ float sigmoidf(float z) {
    return 1.0f / (1.0f + __expf(-z));
}

__device__ __forceinline__ float dot4(float4 v, float4 m) {
    return v.x * m.x + v.y * m.y + v.z * m.z + v.w * m.w;
}

__global__ void __launch_bounds__(64)
probmask_kernel(const float4* __restrict__ x,
                const float4* __restrict__ wv,
                const float4* __restrict__ tv,
                float* __restrict__ out)
{
    int tid  = threadIdx.x;
    int lane = tid & 31;
    int warp = tid >> 5;                        // 0..1

    int blk0  = blockIdx.x << 8;                // block's first pixel (256-aligned)
    int base0 = blk0 + (warp << 7);             // warp's 128-pixel dense tile
    int p     = base0 + lane;

    // 4 dense 512B warp loads issue immediately (no barrier, mask not needed yet).
    float4 v0 = x[p +  0];
    float4 v1 = x[p + 32];
    float4 v2 = x[p + 64];
    float4 v3 = x[p + 96];

    // This thread's single mask entry: h%8 uniform over the block's half-row,
    // w%8 of its pixels (stride 32) = lane&7. Tables are 1KB, L2-resident.
    int h8  = (blk0 >> 9) & 7;
    int mi  = (h8 << 3) + (lane & 7);
    float4 w4 = wv[mi];
    float4 t4 = tv[mi];
    float4 m;
    m.x = sigmoidf(SAMPLE_SLOPE * (sigmoidf(PMASK_SLOPE * w4.x) - t4.x));
    m.y = sigmoidf(SAMPLE_SLOPE * (sigmoidf(PMASK_SLOPE * w4.y) - t4.y));
    m.z = sigmoidf(SAMPLE_SLOPE * (sigmoidf(PMASK_SLOPE * w4.z) - t4.z));
    m.w = sigmoidf(SAMPLE_SLOPE * (sigmoidf(PMASK_SLOPE * w4.w) - t4.w));

    out[p +  0] = dot4(v0, m);
    out[p + 32] = dot4(v1, m);
    out[p + 64] = dot4(v2, m);
    out[p + 96] = dot4(v3, m);
}

extern "C" void kernel_launch(void* const* d_in, const int* in_sizes, int n_in,
                              void* d_out, int out_size)
{
    const float4* x  = (const float4*)d_in[0];
    const float4* wv = (const float4*)d_in[1];
    const float4* tv = (const float4*)d_in[2];
    float* out = (float*)d_out;

    probmask_kernel<<<NBLOCKS, 64>>>(x, wv, tv, out);
}